// round 4
// baseline (speedup 1.0000x reference)
#include <cuda_runtime.h>
#include <cstdint>

// Sinkhorn as diagonal scaling, single persistent cluster kernel.
// out = (s+eps)*u9[r]*v8[c] on the valid block, 0 outside.
// v_{2k} = 1/(M^T u_{2k-1}), u_{2k+1} = 1/(M v_{2k}), u0 = 1 on valid rows.
// One batch == one cluster of 4 CTAs (256 rows each). Column sums are reduced
// across the cluster via DSMEM; all 6 streaming passes run in ONE launch so
// each cluster's ~600KB slice is re-read from L2 with minimal reuse distance.

#define NB   64
#define NN   1024
#define EPS  1e-4f
#define CSZ  4       // CTAs per cluster (one cluster per batch)
#define RPC  256     // rows per CTA
#define RPW  32      // rows per warp (8 warps)

__device__ __forceinline__ uint32_t smem_u32(const void* p) {
    uint32_t a;
    asm("{ .reg .u64 t; cvta.to.shared.u64 t, %1; cvt.u32.u64 %0, t; }"
        : "=r"(a) : "l"(p));
    return a;
}
__device__ __forceinline__ uint32_t mapa_u32(uint32_t local, uint32_t rank) {
    uint32_t r;
    asm("mapa.shared::cluster.u32 %0, %1, %2;" : "=r"(r) : "r"(local), "r"(rank));
    return r;
}
__device__ __forceinline__ float ld_cluster(uint32_t a) {
    float v;
    asm volatile("ld.shared::cluster.f32 %0, [%1];" : "=f"(v) : "r"(a));
    return v;
}
__device__ __forceinline__ void st_cluster(uint32_t a, float v) {
    asm volatile("st.shared::cluster.f32 [%0], %1;" :: "r"(a), "f"(v));
}
// arrive (no .relaxed) = release, wait = acquire: orders shared writes
// (incl. st.shared::cluster) before the barrier against reads after it.
#define CLUSTER_SYNC() do {                                        \
    asm volatile("barrier.cluster.arrive.aligned;" ::: "memory");  \
    asm volatile("barrier.cluster.wait.aligned;"   ::: "memory");  \
} while (0)

__global__ void __cluster_dims__(CSZ, 1, 1) __launch_bounds__(256, 2)
sinkhorn_kernel(const float* __restrict__ s,
                float*       __restrict__ out,
                const int*   __restrict__ nrows,
                const int*   __restrict__ ncols)
{
    __shared__ float  v_s[NN];          // current column scales (0 beyond nc)
    __shared__ float  acc_s[NN];        // this CTA's partial column sums
    __shared__ float4 stage[8][256];    // per-warp accumulator staging

    const int rank = blockIdx.x;        // cluster rank 0..3
    const int b    = blockIdx.y;        // batch
    const int nr   = nrows[b];
    const int nc   = ncols[b];
    const int warp = threadIdx.x >> 5;
    const int lane = threadIdx.x & 31;
    const int mylim = nc - 4 * lane;    // chunk f needed iff 128*f < mylim

    const float4* sb = (const float4*)(s + (size_t)b * NN * NN);
    const int rbase  = rank * RPC + warp * RPW;

    const uint32_t a_acc = smem_u32(acc_s);
    const uint32_t a_v   = smem_u32(v_s);

    // ---- 5 accumulation passes: pass 0 (u=1) -> v0; passes 1..4 -> v2,v4,v6,v8
    for (int pass = 0; pass < 5; pass++) {
        const bool FIRST = (pass == 0);

        float4 v4[8];
        if (!FIRST) {
            const float4* vv = (const float4*)v_s;
#pragma unroll
            for (int f = 0; f < 8; f++)
                v4[f] = (128 * f < mylim) ? vv[f * 32 + lane]
                                          : make_float4(0.f, 0.f, 0.f, 0.f);
        }

        float4 acc[8];
#pragma unroll
        for (int f = 0; f < 8; f++) acc[f] = make_float4(0.f, 0.f, 0.f, 0.f);

        for (int i = 0; i < RPW; i++) {
            int r = rbase + i;
            if (r >= nr) break;                       // warp-uniform
            const float4* rp = sb + (size_t)r * 256;

            float4 x[8];
#pragma unroll
            for (int f = 0; f < 8; f++)
                if (128 * f < mylim) x[f] = rp[f * 32 + lane];
#pragma unroll
            for (int f = 0; f < 8; f++)
                if (128 * f < mylim) {
                    x[f].x += EPS; x[f].y += EPS; x[f].z += EPS; x[f].w += EPS;
                }

            float u = 1.0f;
            if (!FIRST) {
                float d = 0.0f;
#pragma unroll
                for (int f = 0; f < 8; f++)
                    if (128 * f < mylim)
                        d += x[f].x * v4[f].x + x[f].y * v4[f].y
                           + x[f].z * v4[f].z + x[f].w * v4[f].w;
#pragma unroll
                for (int o = 16; o; o >>= 1) d += __shfl_xor_sync(0xffffffffu, d, o);
                u = 1.0f / d;
            }
#pragma unroll
            for (int f = 0; f < 8; f++)
                if (128 * f < mylim) {
                    acc[f].x += x[f].x * u; acc[f].y += x[f].y * u;
                    acc[f].z += x[f].z * u; acc[f].w += x[f].w * u;
                }
        }

        // CTA-level reduction of warp partials into acc_s
#pragma unroll
        for (int f = 0; f < 8; f++) stage[warp][f * 32 + lane] = acc[f];
        __syncthreads();
        {
            const int j = threadIdx.x;                 // owns cols 4j..4j+3
            float4 t = stage[0][j];
#pragma unroll
            for (int w = 1; w < 8; w++) {
                float4 a = stage[w][j];
                t.x += a.x; t.y += a.y; t.z += a.z; t.w += a.w;
            }
            ((float4*)acc_s)[j] = t;
        }

        // Cross-CTA column reduction + v update (sharded: rank owns 256 cols)
        CLUSTER_SYNC();
        {
            const int col = rank * 256 + threadIdx.x;
            float sum = 0.0f;
#pragma unroll
            for (int r = 0; r < CSZ; r++)
                sum += ld_cluster(mapa_u32(a_acc + 4u * col, r));
            const float vn = (col < nc) ? (1.0f / sum) : 0.0f;
#pragma unroll
            for (int r = 0; r < CSZ; r++)
                st_cluster(mapa_u32(a_v + 4u * col, r), vn);
        }
        CLUSTER_SYNC();
        __syncthreads();   // acc_s/stage reuse next pass
    }

    // ---- final pass: u9 = 1/(M v8), write out = (s+eps)*u9*v8
    {
        float4 v4[8];
        const float4* vv = (const float4*)v_s;
#pragma unroll
        for (int f = 0; f < 8; f++)
            v4[f] = (128 * f < mylim) ? vv[f * 32 + lane]
                                      : make_float4(0.f, 0.f, 0.f, 0.f);

        float4* ob = (float4*)(out + (size_t)b * NN * NN);
        const float4 z4 = make_float4(0.f, 0.f, 0.f, 0.f);

        for (int i = 0; i < RPW; i++) {
            int r = rbase + i;
            float4* op = ob + (size_t)r * 256;
            if (r >= nr) {                             // invalid row: zeros
#pragma unroll
                for (int f = 0; f < 8; f++) __stcs(&op[f * 32 + lane], z4);
                continue;
            }
            const float4* rp = sb + (size_t)r * 256;
            float4 x[8];
#pragma unroll
            for (int f = 0; f < 8; f++)
                if (128 * f < mylim) x[f] = rp[f * 32 + lane];
#pragma unroll
            for (int f = 0; f < 8; f++)
                if (128 * f < mylim) {
                    x[f].x += EPS; x[f].y += EPS; x[f].z += EPS; x[f].w += EPS;
                }

            float d = 0.0f;
#pragma unroll
            for (int f = 0; f < 8; f++)
                if (128 * f < mylim)
                    d += x[f].x * v4[f].x + x[f].y * v4[f].y
                       + x[f].z * v4[f].z + x[f].w * v4[f].w;
#pragma unroll
            for (int o = 16; o; o >>= 1) d += __shfl_xor_sync(0xffffffffu, d, o);
            const float u = 1.0f / d;

#pragma unroll
            for (int f = 0; f < 8; f++) {
                if (128 * f < mylim) {
                    float4 o;
                    o.x = x[f].x * u * v4[f].x;
                    o.y = x[f].y * u * v4[f].y;
                    o.z = x[f].z * u * v4[f].z;
                    o.w = x[f].w * u * v4[f].w;
                    __stcs(&op[f * 32 + lane], o);     // v==0 beyond nc -> exact 0
                } else {
                    __stcs(&op[f * 32 + lane], z4);
                }
            }
        }
    }
}

extern "C" void kernel_launch(void* const* d_in, const int* in_sizes, int n_in,
                              void* d_out, int out_size)
{
    const float* s = (const float*)d_in[0];
    const int *nrows, *ncols;
    if (n_in >= 5) {          // order: s, n1, n2, nrows, ncols
        nrows = (const int*)d_in[3];
        ncols = (const int*)d_in[4];
    } else {                  // fallback: s, nrows, ncols
        nrows = (const int*)d_in[1];
        ncols = (const int*)d_in[2];
    }
    float* out = (float*)d_out;

    sinkhorn_kernel<<<dim3(CSZ, NB), 256>>>(s, out, nrows, ncols);
}